// round 3
// baseline (speedup 1.0000x reference)
#include <cuda_runtime.h>

// Problem constants (fixed by the dataset)
#define B_   128
#define E_   100000
#define F_   5000
#define C_   8
#define DIN_ 10
#define DOUT_ 10
#define H_   (F_ * C_)
#define EPS_ 1e-5f

// Transposed scratch (static device mem)
__device__ float g_xT[(size_t)E_ * B_];    // xT[e][b]
__device__ float g_outT[(size_t)E_ * B_];  // outT[e][b] = x + b3, scatter target
__device__ float g_sT[(size_t)H_ * B_];    // sT[h][b]

// ---------------------------------------------------------------------------
// Kernel A: tiled transpose x[b][e] -> xT[e][b], and outT[e][b] = x + b3[e]
// ---------------------------------------------------------------------------
__global__ __launch_bounds__(256)
void transpose_init_kernel(const float* __restrict__ x,
                           const float* __restrict__ b3) {
    __shared__ float tile[32][33];
    const int e0 = blockIdx.x * 32;
    const int b0 = blockIdx.y * 32;
    const int tx = threadIdx.x, ty = threadIdx.y;

#pragma unroll
    for (int k = 0; k < 4; k++) {
        int b = b0 + ty + k * 8;
        tile[ty + k * 8][tx] = x[(size_t)b * E_ + e0 + tx];
    }
    __syncthreads();
#pragma unroll
    for (int k = 0; k < 4; k++) {
        int e = e0 + ty + k * 8;
        float v = tile[tx][ty + k * 8];
        size_t idx = (size_t)e * B_ + b0 + tx;
        g_xT[idx] = v;
        g_outT[idx] = v + b3[e];
    }
}

// ---------------------------------------------------------------------------
// Kernel A2: tiled transpose s[b][h] -> sT[h][b]
// ---------------------------------------------------------------------------
__global__ __launch_bounds__(256)
void transpose_s_kernel(const float* __restrict__ s) {
    __shared__ float tile[32][33];
    const int h0 = blockIdx.x * 32;
    const int b0 = blockIdx.y * 32;
    const int tx = threadIdx.x, ty = threadIdx.y;

#pragma unroll
    for (int k = 0; k < 4; k++) {
        int b = b0 + ty + k * 8;
        tile[ty + k * 8][tx] = s[(size_t)b * H_ + h0 + tx];
    }
    __syncthreads();
#pragma unroll
    for (int k = 0; k < 4; k++) {
        int h = h0 + ty + k * 8;
        g_sT[(size_t)h * B_ + b0 + tx] = tile[tx][ty + k * 8];
    }
}

// ---------------------------------------------------------------------------
// Kernel D: tiled transpose outT[e][b] -> out[b][e]
// ---------------------------------------------------------------------------
__global__ __launch_bounds__(256)
void transpose_out_kernel(float* __restrict__ out) {
    __shared__ float tile[32][33];
    const int e0 = blockIdx.x * 32;
    const int b0 = blockIdx.y * 32;
    const int tx = threadIdx.x, ty = threadIdx.y;

#pragma unroll
    for (int k = 0; k < 4; k++) {
        int e = e0 + ty + k * 8;
        tile[ty + k * 8][tx] = g_outT[(size_t)e * B_ + b0 + tx];
    }
    __syncthreads();
#pragma unroll
    for (int k = 0; k < 4; k++) {
        int b = b0 + ty + k * 8;
        out[(size_t)b * E_ + e0 + tx] = tile[tx][ty + k * 8];
    }
}

__device__ __forceinline__ float elu1(float z) {
    return z > 0.0f ? z : expm1f(z);
}

// Vectorized global reduce-add (sm_90+), 16B per lane.
__device__ __forceinline__ void red_add_v4(float* addr, float a, float b,
                                           float c, float d) {
    asm volatile("red.global.add.v4.f32 [%0], {%1, %2, %3, %4};"
                 :: "l"(addr), "f"(a), "f"(b), "f"(c), "f"(d)
                 : "memory");
}

// ---------------------------------------------------------------------------
// Kernel C: one block per function node f, one thread per batch b (128).
// ---------------------------------------------------------------------------
__global__ __launch_bounds__(B_)
void fn_node_kernel(const float* __restrict__ w1,
                    const float* __restrict__ b1,
                    const float* __restrict__ w2,
                    const float* __restrict__ b2,
                    const float* __restrict__ w3,
                    const int*   __restrict__ src1,   // in_e[f,d] = src1[(f*10+d)*8]
                    const int*   __restrict__ dst3,   // out_e[f,d] = dst3[(f*10+d)*8]
                    const float* __restrict__ g1,
                    const float* __restrict__ bt1,
                    const float* __restrict__ g2,
                    const float* __restrict__ bt2) {
    __shared__ float w1s[DIN_ * C_];
    __shared__ float w2s[C_ * C_];
    __shared__ float w3s[DOUT_ * C_];
    __shared__ int   ine[DIN_];
    __shared__ int   oute[DOUT_];
    __shared__ float b1s[C_], b2s[C_], g1s[C_], bt1s[C_], g2s[C_], bt2s[C_];
    __shared__ __align__(16) float sc[DOUT_][B_];   // scatter staging

    const int f   = blockIdx.x;
    const int tid = threadIdx.x;   // == batch index b

    if (tid < DIN_ * C_)  w1s[tid] = w1[f * (DIN_ * C_) + tid];
    if (tid < C_ * C_)    w2s[tid] = w2[f * (C_ * C_) + tid];
    if (tid < DOUT_ * C_) w3s[tid] = w3[f * (DOUT_ * C_) + tid];
    if (tid < DIN_)       ine[tid]  = src1[(f * DIN_ + tid) * C_];
    if (tid < DOUT_)      oute[tid] = dst3[(f * DOUT_ + tid) * C_];
    if (tid < C_) {
        int hc = f * C_ + tid;
        b1s[tid]  = b1[hc];
        b2s[tid]  = b2[hc];
        g1s[tid]  = g1[hc];
        bt1s[tid] = bt1[hc];
        g2s[tid]  = g2[hc];
        bt2s[tid] = bt2[hc];
    }
    __syncthreads();

    const int b = tid;

    // ---- gather from transposed x: fully coalesced ----
    float xv[DIN_];
#pragma unroll
    for (int d = 0; d < DIN_; d++) xv[d] = __ldg(&g_xT[(size_t)ine[d] * B_ + b]);

    // ---- s from transposed layout: 8 coalesced loads ----
    float sv[C_];
#pragma unroll
    for (int c = 0; c < C_; c++)
        sv[c] = __ldg(&g_sT[(size_t)(f * C_ + c) * B_ + b]);

    // ---- w1: 10x8 dense ----
    float h[C_];
#pragma unroll
    for (int c = 0; c < C_; c++) {
        float acc = b1s[c];
#pragma unroll
        for (int d = 0; d < DIN_; d++) acc = fmaf(xv[d], w1s[d * C_ + c], acc);
        h[c] = acc;
    }

    // ---- groupLN 1 + affine + elu(s*h) ----
    {
        float sum = 0.f, sq = 0.f;
#pragma unroll
        for (int c = 0; c < C_; c++) { sum += h[c]; sq += h[c] * h[c]; }
        float mu  = sum * 0.125f;
        float var = sq * 0.125f - mu * mu;
        float inv = rsqrtf(var + EPS_);
#pragma unroll
        for (int c = 0; c < C_; c++) {
            float z = (g1s[c] * ((h[c] - mu) * inv) + bt1s[c]) * sv[c];
            h[c] = elu1(z);
        }
    }

    // ---- w2: 8x8 dense block ----
    float h2[C_];
#pragma unroll
    for (int c2 = 0; c2 < C_; c2++) {
        float acc = b2s[c2];
#pragma unroll
        for (int c = 0; c < C_; c++) acc = fmaf(h[c], w2s[c * C_ + c2], acc);
        h2[c2] = acc;
    }

    // ---- groupLN 2 + affine + elu(h*s) ----
    {
        float sum = 0.f, sq = 0.f;
#pragma unroll
        for (int c = 0; c < C_; c++) { sum += h2[c]; sq += h2[c] * h2[c]; }
        float mu  = sum * 0.125f;
        float var = sq * 0.125f - mu * mu;
        float inv = rsqrtf(var + EPS_);
#pragma unroll
        for (int c = 0; c < C_; c++) {
            float z = (g2s[c] * ((h2[c] - mu) * inv) + bt2s[c]) * sv[c];
            h[c] = elu1(z);
        }
    }

    // ---- w3: 8 -> 10, stage into smem ----
#pragma unroll
    for (int d = 0; d < DOUT_; d++) {
        float acc = 0.f;
#pragma unroll
        for (int c = 0; c < C_; c++) acc = fmaf(h[c], w3s[d * C_ + c], acc);
        sc[d][b] = acc;
    }
    __syncthreads();

    // ---- vectorized coalesced atomics: 10 edges x 32 float4 lanes ----
#pragma unroll
    for (int i = tid; i < DOUT_ * 32; i += B_) {
        int d = i >> 5;
        int l = i & 31;
        float* dst = &g_outT[(size_t)oute[d] * B_ + l * 4];
        const float* v = &sc[d][l * 4];
        red_add_v4(dst, v[0], v[1], v[2], v[3]);
    }
}

// ---------------------------------------------------------------------------
// Launch
// ---------------------------------------------------------------------------
extern "C" void kernel_launch(void* const* d_in, const int* in_sizes, int n_in,
                              void* d_out, int out_size) {
    const float* x   = (const float*)d_in[0];
    const float* s   = (const float*)d_in[1];
    const float* w1  = (const float*)d_in[2];
    const float* b1  = (const float*)d_in[3];
    const float* w2  = (const float*)d_in[4];
    const float* b2  = (const float*)d_in[5];
    const float* w3  = (const float*)d_in[6];
    const float* b3  = (const float*)d_in[7];
    const float* g1  = (const float*)d_in[8];
    const float* bt1 = (const float*)d_in[9];
    const float* g2  = (const float*)d_in[10];
    const float* bt2 = (const float*)d_in[11];
    const int*   src1 = (const int*)d_in[12];
    const int*   dst3 = (const int*)d_in[17];
    float* out = (float*)d_out;

    dim3 tblk(32, 8);
    transpose_init_kernel<<<dim3(E_ / 32, B_ / 32), tblk>>>(x, b3);
    transpose_s_kernel<<<dim3(H_ / 32, B_ / 32), tblk>>>(s);
    fn_node_kernel<<<F_, B_>>>(w1, b1, w2, b2, w3,
                               src1, dst3, g1, bt1, g2, bt2);
    transpose_out_kernel<<<dim3(E_ / 32, B_ / 32), tblk>>>(out);
}